// round 1
// baseline (speedup 1.0000x reference)
#include <cuda_runtime.h>
#include <cuda_bf16.h>

// Shower accumulator table, packed so the gather phase does ONE 16B L2 read
// per hit instead of four 4B reads.
//   x = e_track_shower (raw)     y = e_track_shower_corr
//   z = e_hit_shower   (raw)     w = e_hit_shower_corr
#define MAX_SEG 16384
__device__ float4 g_shower[MAX_SEG];

// ---------------------------------------------------------------------------
// Kernel 1: zero the accumulator table
// ---------------------------------------------------------------------------
__global__ void zero_kernel(int nseg) {
    int i = blockIdx.x * blockDim.x + threadIdx.x;
    if (i < nseg) g_shower[i] = make_float4(0.f, 0.f, 0.f, 0.f);
}

// ---------------------------------------------------------------------------
// Kernel 2: scatter — segment-sum energies into shower bins.
// Noise hits (sid == -1) contribute exactly 0 (reference zeroes their energy),
// so we simply skip them. recHitID==1 -> track (.x), recHitID==0 -> hit (.z).
// Vectorized int4/float4 loads, 4 hits per thread.
// ---------------------------------------------------------------------------
__global__ void scatter_kernel(const int* __restrict__ sid,
                               const float* __restrict__ energy,
                               const int* __restrict__ rid,
                               int n) {
    int t = blockIdx.x * blockDim.x + threadIdx.x;
    int base = t * 4;
    if (base + 4 <= n) {
        int4   s4 = __ldg((const int4*)(sid) + t);
        float4 e4 = __ldg((const float4*)(energy) + t);
        int4   r4 = __ldg((const int4*)(rid) + t);
        int   s[4] = {s4.x, s4.y, s4.z, s4.w};
        float e[4] = {e4.x, e4.y, e4.z, e4.w};
        int   r[4] = {r4.x, r4.y, r4.z, r4.w};
#pragma unroll
        for (int k = 0; k < 4; k++) {
            if (s[k] >= 0) {
                float* p = reinterpret_cast<float*>(&g_shower[s[k] + 1]);
                // track -> offset 0 (.x), hit -> offset 2 (.z)
                atomicAdd(p + (r[k] == 1 ? 0 : 2), e[k]);
            }
        }
    } else if (base < n) {
        for (int i = base; i < n; i++) {
            int sv = sid[i];
            if (sv >= 0) {
                float* p = reinterpret_cast<float*>(&g_shower[sv + 1]);
                atomicAdd(p + (rid[i] == 1 ? 0 : 2), energy[i]);
            }
        }
    }
}

// ---------------------------------------------------------------------------
// Kernel 3: per-shower correction factors.
// corr[s] (s>=1) = pcf_ext[alpha_idx[s-1]] where pcf_ext[j] = pcf[j] if
// j < n_hits and sid[j] != -1, else 0 (covers both the noise zeroing and the
// appended zero row at index n_hits). corr[0] = 0.
// ---------------------------------------------------------------------------
__global__ void corr_kernel(const int* __restrict__ sid,
                            const float* __restrict__ pcf,
                            const int* __restrict__ a_tracks,
                            const int* __restrict__ a_hits,
                            int n_hits, int nseg) {
    int s = blockIdx.x * blockDim.x + threadIdx.x;
    if (s >= nseg) return;
    float ct = 0.f, ch = 0.f;
    if (s > 0) {
        int jt = a_tracks[s - 1];
        if (jt >= 0 && jt < n_hits && __ldg(sid + jt) != -1) ct = __ldg(pcf + jt);
        int jh = a_hits[s - 1];
        if (jh >= 0 && jh < n_hits && __ldg(sid + jh) != -1) ch = __ldg(pcf + jh);
    }
    float4 v = g_shower[s];
    g_shower[s].y = v.x * ct;   // track corrected
    g_shower[s].w = v.z * ch;   // hit corrected
}

// ---------------------------------------------------------------------------
// Kernel 4: gather — one 16B L2 read per hit, four coalesced float4 stores.
// Output layout (metadata order of the reference tuple):
//   [0,n)   e_track_raw   [n,2n)  e_track_corrected
//   [2n,3n) e_hit_raw     [3n,4n) e_hit_corrected
// ---------------------------------------------------------------------------
__global__ void gather_kernel_vec(const int* __restrict__ sid,
                                  float* __restrict__ out,
                                  int n) {
    int t = blockIdx.x * blockDim.x + threadIdx.x;
    if (t * 4 >= n) return;
    int4 s4 = __ldg((const int4*)(sid) + t);
    float4 v0 = g_shower[s4.x + 1];
    float4 v1 = g_shower[s4.y + 1];
    float4 v2 = g_shower[s4.z + 1];
    float4 v3 = g_shower[s4.w + 1];
    float4* o0 = (float4*)(out)         + t;
    float4* o1 = (float4*)(out + n)     + t;
    float4* o2 = (float4*)(out + 2ll*n) + t;
    float4* o3 = (float4*)(out + 3ll*n) + t;
    *o0 = make_float4(v0.x, v1.x, v2.x, v3.x);  // track raw
    *o1 = make_float4(v0.y, v1.y, v2.y, v3.y);  // track corrected
    *o2 = make_float4(v0.z, v1.z, v2.z, v3.z);  // hit raw
    *o3 = make_float4(v0.w, v1.w, v2.w, v3.w);  // hit corrected
}

__global__ void gather_kernel_scalar(const int* __restrict__ sid,
                                     float* __restrict__ out,
                                     int n) {
    int i = blockIdx.x * blockDim.x + threadIdx.x;
    if (i >= n) return;
    float4 v = g_shower[sid[i] + 1];
    out[i]          = v.x;
    out[i + 1ll*n]  = v.y;
    out[i + 2ll*n]  = v.z;
    out[i + 3ll*n]  = v.w;
}

extern "C" void kernel_launch(void* const* d_in, const int* in_sizes, int n_in,
                              void* d_out, int out_size) {
    const int*   pred_sid = (const int*)  d_in[0];
    const float* pcf      = (const float*)d_in[1];
    const float* energy   = (const float*)d_in[2];
    const int*   rid      = (const int*)  d_in[3];
    // d_in[4] = pred_beta (unused)
    const int*   a_tracks = (const int*)  d_in[5];
    const int*   a_hits   = (const int*)  d_in[6];
    float*       out      = (float*)d_out;

    int n_hits    = in_sizes[0];
    int n_showers = in_sizes[5];
    int nseg      = n_showers + 1;
    if (nseg > MAX_SEG) nseg = MAX_SEG;

    const int TPB = 256;

    zero_kernel<<<(nseg + TPB - 1) / TPB, TPB>>>(nseg);

    int n4 = (n_hits + 3) / 4;
    scatter_kernel<<<(n4 + TPB - 1) / TPB, TPB>>>(pred_sid, energy, rid, n_hits);

    corr_kernel<<<(nseg + TPB - 1) / TPB, TPB>>>(pred_sid, pcf, a_tracks, a_hits,
                                                 n_hits, nseg);

    if ((n_hits & 3) == 0) {
        gather_kernel_vec<<<(n4 + TPB - 1) / TPB, TPB>>>(pred_sid, out, n_hits);
    } else {
        gather_kernel_scalar<<<(n_hits + TPB - 1) / TPB, TPB>>>(pred_sid, out, n_hits);
    }
}